// round 5
// baseline (speedup 1.0000x reference)
#include <cuda_runtime.h>
#include <math.h>

#define Hd 512
#define Wd 512
#define NPTS 2048           // 64 segments * 32 samples
#define NT 512
#define RADIUS 12.0f        // sigma(-12) = 6.1e-6 truncation
#define NBIN 16             // 32-pixel column bins
#define CAP 256             // per-bin active-edge capacity (smem)
#define CAPR 1024           // per-row edge-list capacity (gmem)

// Persistent scratch (allocation-free): edge table + per-row edge lists.
__device__ float4         g_edge[NPTS];
__device__ unsigned short g_list[Hd][CAPR];
__device__ int            g_cnt[Hd];          // zero-init; render resets per row

__device__ __forceinline__ float fsig(float z) {
    return __fdividef(1.0f, 1.0f + __expf(-z));
}

__device__ __forceinline__ float2 bez(const float2* c2, int idx) {
    int seg = idx >> 5;
    int k   = idx & 31;
    float t  = (float)k * (1.0f / 31.0f);
    float mt = 1.0f - t;
    float2 p0 = c2[3 * seg + 0];
    float2 p1 = c2[3 * seg + 1];
    float2 p2 = c2[3 * seg + 2];
    float2 p3 = c2[3 * seg + 3];
    float w0 = mt * mt * mt;
    float w1 = 3.0f * mt * mt * t;
    float w2 = 3.0f * mt * t * t;
    float w3 = t * t * t;
    return make_float2(w0 * p0.x + w1 * p1.x + w2 * p2.x + w3 * p3.x,
                       w0 * p0.y + w1 * p1.y + w2 * p2.y + w3 * p3.y);
}

// ---- Kernel 1: per-edge data + scatter edge index into active rows ----
__global__ __launch_bounds__(NT)
void build_edges(const float* __restrict__ cp) {
    int e = blockIdx.x * NT + threadIdx.x;          // 0..2047
    const float2* c2 = (const float2*)cp;
    float2 a = bez(c2, e);
    float2 b = bez(c2, (e + 1) & (NPTS - 1));
    float dy = b.y - a.y;
    if (fabsf(dy) < 1e-6f) return;                  // reference mask==0
    float dyp = dy + 1e-8f;
    g_edge[e] = make_float4(a.x, a.y, b.x - a.x, 1.0f / dyp);

    // active rows: t in [-1, 2]  <=>  gy in [y0 - dyp, y0 + 2 dyp] (sign-aware)
    float ylo = a.y - dyp, yhi = a.y + 2.0f * dyp;
    if (dyp < 0.0f) { float s = ylo; ylo = yhi; yhi = s; }
    int r0 = max(0, (int)ceilf(ylo));
    int r1 = min(Hd - 1, (int)floorf(yhi));
    for (int r = r0; r <= r1; ++r) {
        int p = atomicAdd(&g_cnt[r], 1);
        if (p < CAPR) g_list[r][p] = (unsigned short)e;
    }
}

// ---- Kernel 2: one block per row; pixel-per-thread register accumulation ----
__global__ __launch_bounds__(NT)
void render_rows(const float* __restrict__ color, float* __restrict__ out) {
    __shared__ float2 s_bin[NBIN][CAP];   // binned active edges (xc, w)
    __shared__ int    s_cnt[NBIN];
    __shared__ float  s_carry[Wd + 1];    // full-weight step buckets
    __shared__ float  s_wsum[16];

    const int tid = threadIdx.x;
    const int y   = blockIdx.x;
    const float gy = (float)y;

    s_carry[tid] = 0.0f;
    if (tid == 0) s_carry[Wd] = 0.0f;
    if (tid < NBIN) s_cnt[tid] = 0;
    __syncthreads();

    // --- Phase A: process this row's edge list only (~60-300 edges) ---
    int n = min(g_cnt[y], CAPR);
    for (int i = tid; i < n; i += NT) {
        int e = g_list[y][i];
        float4 E = g_edge[e];                      // (x0, y0, dx, inv_dy)
        float t = (gy - E.y) * E.w;                // in [-1,2] by construction
        float w = fsig(20.0f * t) * fsig(20.0f - 20.0f * t);
        w = copysignf(w, E.w);                     // sign(dy)
        float xc = fmaf(t, E.z, E.x);

        // full weight for x < ceil(xc - R) -> carry bucket
        int ci = min(max((int)ceilf(xc - RADIUS), 0), Wd);
        atomicAdd(&s_carry[ci], w);

        // transition window -> spatial bin by xc
        int bi = min(max((int)floorf(xc * (1.0f / 32.0f)), 0), NBIN - 1);
        int p  = atomicAdd(&s_cnt[bi], 1);
        if (p < CAP) s_bin[bi][p] = make_float2(xc, w);
    }
    __syncthreads();

    // --- Phase B: thread owns pixel x = tid; warp scans its 3 nearby bins ---
    float wind = 0.0f;
    {
        const float fx = (float)tid;
        const int wp = tid >> 5;
        const int b0 = max(wp - 1, 0);
        const int b1 = min(wp + 1, NBIN - 1);
        for (int b = b0; b <= b1; ++b) {
            int m = min(s_cnt[b], CAP);
            for (int i = 0; i < m; ++i) {
                float2 E = s_bin[b][i];            // broadcast LDS
                float z = E.x - fx;
                if (fabsf(z) <= RADIUS)
                    wind += E.y * fsig(z);         // x>=ci <=> z<=R
            }
        }
    }
    __syncthreads();

    // --- suffix scan of carry: P[tid] = sum_{j >= 512-tid} carry[j] ---
    float v = s_carry[Wd - tid];
    __syncthreads();
    const int lane = tid & 31, wid = tid >> 5;
    float val = v;
    #pragma unroll
    for (int o = 1; o < 32; o <<= 1) {
        float nb = __shfl_up_sync(0xffffffffu, val, o);
        if (lane >= o) val += nb;
    }
    if (lane == 31) s_wsum[wid] = val;
    __syncthreads();
    if (wid == 0) {
        float s = (lane < 16) ? s_wsum[lane] : 0.0f;
        #pragma unroll
        for (int o = 1; o < 16; o <<= 1) {
            float nb = __shfl_up_sync(0xffffffffu, s, o);
            if (lane >= o) s += nb;
        }
        if (lane < 16) s_wsum[lane] = s;
    }
    __syncthreads();
    if (wid > 0) val += s_wsum[wid - 1];
    s_carry[tid] = val;                            // P[tid]
    __syncthreads();

    // --- output: wind += sum_{j > x} carry[j] = P[511 - x] ---
    wind += s_carry[(Wd - 1) - tid];
    float alpha = fsig(4.0f * wind);
    ((float4*)out)[y * Wd + tid] =
        make_float4(color[0], color[1], color[2], alpha);

    // reset this row's counter for the next graph replay (deterministic)
    if (tid == 0) g_cnt[y] = 0;
}

extern "C" void kernel_launch(void* const* d_in, const int* in_sizes, int n_in,
                              void* d_out, int out_size) {
    (void)in_sizes; (void)n_in; (void)out_size;
    const float* cp    = (const float*)d_in[0];   // (193,2) float32
    const float* color = (const float*)d_in[1];   // (3,)    float32
    float* out = (float*)d_out;                   // (512,512,4) float32
    build_edges<<<NPTS / NT, NT>>>(cp);
    render_rows<<<Hd, NT>>>(color, out);
}

// round 6
// speedup vs baseline: 3.7932x; 3.7932x over previous
#include <cuda_runtime.h>
#include <math.h>

#define Hd 512
#define Wd 512
#define NPTS 2048           // 64 segments * 32 samples
#define NT 512
#define RADIUS 12.0f        // sigma(-12) = 6.1e-6 truncation
#define NBIN 16             // 32-pixel column bins, one per warp
#define CAP 256             // per-bin active-edge capacity (smem)
#define CAPR 1024           // per-row edge-list capacity (gmem)

// Persistent scratch (allocation-free): edge table + per-row edge lists.
__device__ float4         g_edge[NPTS];
__device__ unsigned short g_list[Hd][CAPR];
__device__ int            g_cnt[Hd];          // zero-init; render resets per row

__device__ __forceinline__ float fsig(float z) {
    return __fdividef(1.0f, 1.0f + __expf(-z));
}

__device__ __forceinline__ float2 bez(const float2* c2, int idx) {
    int seg = idx >> 5;
    int k   = idx & 31;
    float t  = (float)k * (1.0f / 31.0f);
    float mt = 1.0f - t;
    float2 p0 = c2[3 * seg + 0];
    float2 p1 = c2[3 * seg + 1];
    float2 p2 = c2[3 * seg + 2];
    float2 p3 = c2[3 * seg + 3];
    float w0 = mt * mt * mt;
    float w1 = 3.0f * mt * mt * t;
    float w2 = 3.0f * mt * t * t;
    float w3 = t * t * t;
    return make_float2(w0 * p0.x + w1 * p1.x + w2 * p2.x + w3 * p3.x,
                       w0 * p0.y + w1 * p1.y + w2 * p2.y + w3 * p3.y);
}

// ---- Kernel 1: one WARP per edge; lanes scatter the edge's active rows ----
__global__ __launch_bounds__(NT)
void build_edges(const float* __restrict__ cp) {
    const int lane = threadIdx.x & 31;
    const int e = (blockIdx.x * NT + threadIdx.x) >> 5;   // warp id == edge id
    const float2* c2 = (const float2*)cp;

    float2 a = bez(c2, e);
    float2 b = bez(c2, (e + 1) & (NPTS - 1));
    float dy = b.y - a.y;
    if (fabsf(dy) < 1e-6f) return;                  // reference mask==0
    float dyp = dy + 1e-8f;
    if (lane == 0)
        g_edge[e] = make_float4(a.x, a.y, b.x - a.x, 1.0f / dyp);

    // active rows: t in [-1, 2]  <=>  gy in [y0 - dyp, y0 + 2 dyp] (sign-aware)
    float ylo = a.y - dyp, yhi = a.y + 2.0f * dyp;
    if (dyp < 0.0f) { float s = ylo; ylo = yhi; yhi = s; }
    int r0 = max(0, (int)ceilf(ylo));
    int r1 = min(Hd - 1, (int)floorf(yhi));
    for (int r = r0 + lane; r <= r1; r += 32) {     // parallel scatter
        int p = atomicAdd(&g_cnt[r], 1);
        if (p < CAPR) g_list[r][p] = (unsigned short)e;
    }
}

// ---- Kernel 2: one block per row; warp w owns pixels [32w, 32w+31] ----
__global__ __launch_bounds__(NT)
void render_rows(const float* __restrict__ color, float* __restrict__ out) {
    __shared__ float2 s_bin[NBIN][CAP];   // per-warp active edges (xc, w)
    __shared__ int    s_cnt[NBIN];
    __shared__ float  s_carry[Wd + 1];    // full-weight step buckets
    __shared__ float  s_wsum[16];

    const int tid = threadIdx.x;
    const int y   = blockIdx.x;
    const float gy = (float)y;

    s_carry[tid] = 0.0f;
    if (tid == 0) s_carry[Wd] = 0.0f;
    if (tid < NBIN) s_cnt[tid] = 0;
    __syncthreads();

    // --- Phase A: this row's edge list only; insert window into ALL bins it spans ---
    int n = min(g_cnt[y], CAPR);
    for (int i = tid; i < n; i += NT) {
        int e = g_list[y][i];
        float4 E = g_edge[e];                      // (x0, y0, dx, inv_dy)
        float t = (gy - E.y) * E.w;                // in [-1,2] by construction
        float w = fsig(20.0f * t) * fsig(20.0f - 20.0f * t);
        w = copysignf(w, E.w);                     // sign(dy)
        float xc = fmaf(t, E.z, E.x);

        // full weight for x < ceil(xc - R) -> carry bucket (once per edge)
        int ci = min(max((int)ceilf(xc - RADIUS), 0), Wd);
        atomicAdd(&s_carry[ci], w);

        // window [xc-R, xc+R] -> every 32px bin it overlaps (<= 2 bins)
        int b0 = max((int)floorf((xc - RADIUS) * (1.0f / 32.0f)), 0);
        int b1 = min((int)floorf((xc + RADIUS) * (1.0f / 32.0f)), NBIN - 1);
        for (int b = b0; b <= b1; ++b) {
            int p = atomicAdd(&s_cnt[b], 1);
            if (p < CAP) s_bin[b][p] = make_float2(xc, w);
        }
    }
    __syncthreads();

    // --- Phase B: warp scans exactly its own bin ---
    float wind = 0.0f;
    {
        const float fx = (float)tid;
        const int wp = tid >> 5;
        const int m = min(s_cnt[wp], CAP);
        for (int i = 0; i < m; ++i) {
            float2 E = s_bin[wp][i];               // broadcast LDS
            float z = E.x - fx;
            if (fabsf(z) <= RADIUS)
                wind += E.y * fsig(z);             // x>=ci <=> z<=R
        }
    }
    __syncthreads();

    // --- suffix scan of carry: P[tid] = sum_{j >= 512-tid} carry[j] ---
    float v = s_carry[Wd - tid];
    __syncthreads();
    const int lane = tid & 31, wid = tid >> 5;
    float val = v;
    #pragma unroll
    for (int o = 1; o < 32; o <<= 1) {
        float nb = __shfl_up_sync(0xffffffffu, val, o);
        if (lane >= o) val += nb;
    }
    if (lane == 31) s_wsum[wid] = val;
    __syncthreads();
    if (wid == 0) {
        float s = (lane < 16) ? s_wsum[lane] : 0.0f;
        #pragma unroll
        for (int o = 1; o < 16; o <<= 1) {
            float nb = __shfl_up_sync(0xffffffffu, s, o);
            if (lane >= o) s += nb;
        }
        if (lane < 16) s_wsum[lane] = s;
    }
    __syncthreads();
    if (wid > 0) val += s_wsum[wid - 1];
    s_carry[tid] = val;                            // P[tid]
    __syncthreads();

    // --- output: wind += sum_{j > x} carry[j] = P[511 - x] ---
    wind += s_carry[(Wd - 1) - tid];
    float alpha = fsig(4.0f * wind);
    ((float4*)out)[y * Wd + tid] =
        make_float4(color[0], color[1], color[2], alpha);

    // reset this row's counter for the next graph replay (deterministic)
    if (tid == 0) g_cnt[y] = 0;
}

extern "C" void kernel_launch(void* const* d_in, const int* in_sizes, int n_in,
                              void* d_out, int out_size) {
    (void)in_sizes; (void)n_in; (void)out_size;
    const float* cp    = (const float*)d_in[0];   // (193,2) float32
    const float* color = (const float*)d_in[1];   // (3,)    float32
    float* out = (float*)d_out;                   // (512,512,4) float32
    build_edges<<<NPTS * 32 / NT, NT>>>(cp);      // 128 blocks, warp per edge
    render_rows<<<Hd, NT>>>(color, out);
}